// round 9
// baseline (speedup 1.0000x reference)
#include <cuda_runtime.h>
#include <cstdint>

// Scratch (no cudaMalloc allowed)
__device__ float2 g_Mpack[64 * 32];   // g_Mpack[i*32+l] = (exp(T[i][l]), exp(T[i][l+32]))
__device__ float  g_loss[4096];
__device__ int    g_order[4096];
__device__ int    g_done;

// ---------- f32x2 packed math ----------
static __device__ __forceinline__ unsigned long long pack2f(float lo, float hi) {
    unsigned long long r;
    asm("mov.b64 %0, {%1, %2};" : "=l"(r) : "f"(lo), "f"(hi));
    return r;
}
static __device__ __forceinline__ void unpack2f(unsigned long long v, float& lo, float& hi) {
    asm("mov.b64 {%0, %1}, %2;" : "=f"(lo), "=f"(hi) : "l"(v));
}
static __device__ __forceinline__ unsigned long long ffma2(unsigned long long a,
                                                           unsigned long long b,
                                                           unsigned long long c) {
    unsigned long long d;
    asm("fma.rn.f32x2 %0, %1, %2, %3;" : "=l"(d) : "l"(a), "l"(b), "l"(c));
    return d;
}
static __device__ __forceinline__ unsigned long long fadd2(unsigned long long a,
                                                           unsigned long long b) {
    unsigned long long d;
    asm("add.rn.f32x2 %0, %1, %2;" : "=l"(d) : "l"(a), "l"(b));
    return d;
}
static __device__ __forceinline__ unsigned long long fmul2(unsigned long long a,
                                                           unsigned long long b) {
    unsigned long long d;
    asm("mul.rn.f32x2 %0, %1, %2;" : "=l"(d) : "l"(a), "l"(b));
    return d;
}

// ---------- kernel 0: fused prep (Mpack + hist + scan + scatter + counter reset) ----------
__global__ void __launch_bounds__(1024) crf_prep(const float* __restrict__ trans,
                                                 const int* __restrict__ seq_len, int B) {
    __shared__ int h[513], f[513], off[513];
    __shared__ int sc[1024];
    const int tid = threadIdx.x;

    if (tid < 513) { h[tid] = 0; f[tid] = 0; }
    for (int idx = tid; idx < 64 * 32; idx += 1024) {
        int i = idx >> 5, l = idx & 31;
        g_Mpack[idx] = make_float2(__expf(trans[i * 64 + l]),
                                   __expf(trans[i * 64 + l + 32]));
    }
    __syncthreads();

    for (int b = tid; b < B; b += 1024) {
        int s = seq_len[b];
        s = max(0, min(512, s));
        atomicAdd(&h[s], 1);
    }
    __syncthreads();

    sc[tid] = (tid < 513) ? h[512 - tid] : 0;   // reversed (descending S)
    __syncthreads();
    for (int d = 1; d < 1024; d <<= 1) {
        int v = (tid >= d) ? sc[tid - d] : 0;
        __syncthreads();
        sc[tid] += v;
        __syncthreads();
    }
    if (tid < 513) off[512 - tid] = sc[tid] - h[512 - tid];
    __syncthreads();

    for (int b = tid; b < B; b += 1024) {
        int s = seq_len[b];
        s = max(0, min(512, s));
        int pos = off[s] + atomicAdd(&f[s], 1);
        if (pos < 4096) g_order[pos] = b;
    }
    if (tid == 0) g_done = 0;
}

// ---------- kernel 1: forward (R8 body); 2 warps/SMSP with complement pairing ----------
// warpIn 0-3 take sorted rank blk*4+warpIn (long rows); warpIn 4-7 take the
// complement B-1-rank (short rows). Each SMSP's warp pair sums to ~513 steps.
__global__ void __launch_bounds__(256, 1) crf_forward(
    const float* __restrict__ pred,     // [B, T, 62]
    const int*   __restrict__ ref,      // [B, T]
    const int*   __restrict__ seq_len,  // [B]
    const float* __restrict__ trans,    // [64, 64]
    float* __restrict__ out,
    int B, int T)
{
    const int lane   = threadIdx.x & 31;
    const int warpIn = threadIdx.x >> 5;          // 0..7

    __shared__ __align__(16) float alphaSh[8][64];
    __shared__ int s_last;
    __shared__ double s_red[256];
    float* aS = alphaSh[warpIn];

    // M columns (lane, lane+32) in registers: 64 x f32x2
    unsigned long long Mreg[64];
#pragma unroll
    for (int i = 0; i < 64; i++)
        Mreg[i] = *reinterpret_cast<const unsigned long long*>(&g_Mpack[i * 32 + lane]);

    const float T_lo = g_Mpack[lane * 32 + 31].y;          // exp(trans[lane][63])
    const float T_hi = g_Mpack[(lane + 32) * 32 + 31].y;   // exp(trans[lane+32][63])

    // complement row assignment
    const int half = (B + 1) >> 1;
    int idx;
    bool active;
    if (warpIn < 4) {
        idx = blockIdx.x * 4 + warpIn;
        active = (idx < half);
    } else {
        idx = B - 1 - (blockIdx.x * 4 + (warpIn - 4));
        active = (idx >= half && idx < B);
    }

    if (active) {
        const int b = g_order[idx];
        const int S = seq_len[b];
        const float* prow = pred + (size_t)b * T * 62;

        // init alpha = ones over 62 labels, C = -1000 (b_s floor)
        aS[lane]      = 1.0f;
        aS[lane + 32] = (lane < 30) ? 1.0f : 0.0f;
        __syncwarp();

        float C = -1000.0f;
        float escale = 1.0f;      // pending 1/s, folded into next chunk's first emission
        float v_lo = 1.0f, v_hi = (lane < 30) ? 1.0f : 0.0f;

        const int nch = (S + 3) >> 2;

        // triple-buffered emission prefetch (4 steps per buffer)
        float plo0[4], phi0[4], plo1[4], phi1[4], plo2[4], phi2[4];

        auto loadch = [&](float (&lo)[4], float (&hi)[4], int c) {
#pragma unroll
            for (int k = 0; k < 4; k++) {
                int u = c * 4 + k;
                if (u < S) {
                    const float* rp = prow + (size_t)u * 62;
                    lo[k] = rp[lane];
                    hi[k] = (lane < 30) ? rp[lane + 32] : 0.0f;
                } else { lo[k] = 0.0f; hi[k] = 0.0f; }
            }
        };

        loadch(plo0, phi0, 0);
        if (nch > 1) loadch(plo1, phi1, 1);

        for (int c = 0; c < nch; c++) {
            if (c + 2 < nch) loadch(plo2, phi2, c + 2);

#pragma unroll
            for (int k = 0; k < 4; k++) {
                int u = c * 4 + k;
                if (u < S) {
                    float sc = (k == 0) ? escale : 1.0f;
                    float e_lo = __expf(plo0[k]) * sc;
                    float e_hi = (lane < 30) ? __expf(phi0[k]) * sc : 0.0f;

                    // matvec: acc[j] = sum_i alpha[i]*M[i][j], 8 accumulators
                    unsigned long long a0 = 0, a1 = 0, a2 = 0, a3 = 0,
                                       a4 = 0, a5 = 0, a6 = 0, a7 = 0;
#pragma unroll
                    for (int i = 0; i < 64; i += 8) {
                        float4 x = *reinterpret_cast<const float4*>(&aS[i]);
                        float4 y = *reinterpret_cast<const float4*>(&aS[i + 4]);
                        a0 = ffma2(pack2f(x.x, x.x), Mreg[i + 0], a0);
                        a1 = ffma2(pack2f(x.y, x.y), Mreg[i + 1], a1);
                        a2 = ffma2(pack2f(x.z, x.z), Mreg[i + 2], a2);
                        a3 = ffma2(pack2f(x.w, x.w), Mreg[i + 3], a3);
                        a4 = ffma2(pack2f(y.x, y.x), Mreg[i + 4], a4);
                        a5 = ffma2(pack2f(y.y, y.y), Mreg[i + 5], a5);
                        a6 = ffma2(pack2f(y.z, y.z), Mreg[i + 6], a6);
                        a7 = ffma2(pack2f(y.w, y.w), Mreg[i + 7], a7);
                    }
                    unsigned long long acc =
                        fadd2(fadd2(fadd2(a0, a1), fadd2(a2, a3)),
                              fadd2(fadd2(a4, a5), fadd2(a6, a7)));
                    unsigned long long v2 = fmul2(acc, pack2f(e_lo, e_hi));
                    unpack2f(v2, v_lo, v_hi);

                    __syncwarp();
                    aS[lane]      = v_lo;
                    aS[lane + 32] = v_hi;
                    __syncwarp();
                }
            }

            // renormalize once per chunk (exact; lazily applied next chunk)
            if (c + 1 < nch) {
                float s = v_lo + v_hi;
#pragma unroll
                for (int m = 16; m >= 1; m >>= 1)
                    s += __shfl_xor_sync(0xffffffffu, s, m);
                C += __logf(s);
                escale = __fdividef(1.0f, s);
            }

            // rotate prefetch buffers
#pragma unroll
            for (int k = 0; k < 4; k++) {
                plo0[k] = plo1[k]; phi0[k] = phi1[k];
                plo1[k] = plo2[k]; phi1[k] = phi2[k];
            }
        }

        // logZ = C + log( sum_i v[i] * exp(trans[i,63]) )
        float z = v_lo * T_lo + v_hi * T_hi;
#pragma unroll
        for (int m = 16; m >= 1; m >>= 1)
            z += __shfl_xor_sync(0xffffffffu, z, m);
        float logZ = C + __logf(z);

        // gold path score
        float gold = 0.0f;
        const int* refb = ref + (size_t)b * T;
        for (int t = lane; t < S; t += 32) {
            int rt = refb[t];
            gold += prow[(size_t)t * 62 + rt];             // emission
            int rp = (t == 0) ? 62 : refb[t - 1];          // start row at t=0
            gold += trans[rp * 64 + rt];                   // transition
        }
        if (lane == 0)
            gold += trans[refb[S - 1] * 64 + 63];          // final -> end
#pragma unroll
        for (int m = 16; m >= 1; m >>= 1)
            gold += __shfl_xor_sync(0xffffffffu, gold, m);

        if (lane == 0 && b < 4096)
            g_loss[b] = logZ - gold;
    }

    // ---- fused deterministic reduction: last CTA sums in fixed order ----
    __syncthreads();
    if (threadIdx.x == 0) {
        __threadfence();
        int v = atomicAdd(&g_done, 1);
        s_last = (v == gridDim.x - 1) ? 1 : 0;
    }
    __syncthreads();
    if (s_last) {
        __threadfence();
        double acc = 0.0;
        for (int i = threadIdx.x; i < B; i += 256)
            acc += (double)g_loss[i];
        s_red[threadIdx.x] = acc;
        __syncthreads();
        for (int st = 128; st >= 1; st >>= 1) {
            if (threadIdx.x < st) s_red[threadIdx.x] += s_red[threadIdx.x + st];
            __syncthreads();
        }
        if (threadIdx.x == 0) out[0] = (float)s_red[0];
    }
}

extern "C" void kernel_launch(void* const* d_in, const int* in_sizes, int n_in,
                              void* d_out, int out_size) {
    const float* pred   = (const float*)d_in[0];
    const int*   ref    = (const int*)d_in[1];
    const int*   seqlen = (const int*)d_in[2];
    const float* trans  = (const float*)d_in[3];

    int B = in_sizes[2];            // 1024
    int T = in_sizes[1] / B;        // 512

    int ctas = ((B + 1) / 2 + 3) / 4;   // 128 for B=1024

    crf_prep<<<1, 1024>>>(trans, seqlen, B);
    crf_forward<<<ctas, 256>>>(pred, ref, seqlen, trans, (float*)d_out, B, T);
}

// round 15
// speedup vs baseline: 1.4091x; 1.4091x over previous
#include <cuda_runtime.h>
#include <cstdint>

// Scratch (no cudaMalloc allowed)
__device__ float2 g_Mpack[64 * 32];   // g_Mpack[i*32+l] = (exp(T[i][l]), exp(T[i][l+32]))
__device__ float  g_loss[4096];
__device__ int    g_order[4096];
__device__ int    g_done;

// ---------- f32x2 packed math ----------
static __device__ __forceinline__ unsigned long long pack2f(float lo, float hi) {
    unsigned long long r;
    asm("mov.b64 %0, {%1, %2};" : "=l"(r) : "f"(lo), "f"(hi));
    return r;
}
static __device__ __forceinline__ void unpack2f(unsigned long long v, float& lo, float& hi) {
    asm("mov.b64 {%0, %1}, %2;" : "=f"(lo), "=f"(hi) : "l"(v));
}
static __device__ __forceinline__ unsigned long long ffma2(unsigned long long a,
                                                           unsigned long long b,
                                                           unsigned long long c) {
    unsigned long long d;
    asm("fma.rn.f32x2 %0, %1, %2, %3;" : "=l"(d) : "l"(a), "l"(b), "l"(c));
    return d;
}
static __device__ __forceinline__ unsigned long long fadd2(unsigned long long a,
                                                           unsigned long long b) {
    unsigned long long d;
    asm("add.rn.f32x2 %0, %1, %2;" : "=l"(d) : "l"(a), "l"(b));
    return d;
}
static __device__ __forceinline__ unsigned long long fmul2(unsigned long long a,
                                                           unsigned long long b) {
    unsigned long long d;
    asm("mul.rn.f32x2 %0, %1, %2;" : "=l"(d) : "l"(a), "l"(b));
    return d;
}
// full warp sum (5-SHFL tree) — used only once per row
static __device__ __forceinline__ float warp_sum(float v) {
#pragma unroll
    for (int m = 16; m >= 1; m >>= 1)
        v += __shfl_xor_sync(0xffffffffu, v, m);
    return v;
}

// ---------- kernel 0: fused prep (Mpack + hist + scan + scatter + counter reset) ----------
__global__ void __launch_bounds__(1024) crf_prep(const float* __restrict__ trans,
                                                 const int* __restrict__ seq_len, int B) {
    __shared__ int h[513], f[513], off[513];
    __shared__ int sc[1024];
    const int tid = threadIdx.x;

    if (tid < 513) { h[tid] = 0; f[tid] = 0; }
    for (int idx = tid; idx < 64 * 32; idx += 1024) {
        int i = idx >> 5, l = idx & 31;
        g_Mpack[idx] = make_float2(__expf(trans[i * 64 + l]),
                                   __expf(trans[i * 64 + l + 32]));
    }
    __syncthreads();

    for (int b = tid; b < B; b += 1024) {
        int s = seq_len[b];
        s = max(0, min(512, s));
        atomicAdd(&h[s], 1);
    }
    __syncthreads();

    sc[tid] = (tid < 513) ? h[512 - tid] : 0;   // reversed (descending S)
    __syncthreads();
    for (int d = 1; d < 1024; d <<= 1) {
        int v = (tid >= d) ? sc[tid - d] : 0;
        __syncthreads();
        sc[tid] += v;
        __syncthreads();
    }
    if (tid < 513) off[512 - tid] = sc[tid] - h[512 - tid];
    __syncthreads();

    for (int b = tid; b < B; b += 1024) {
        int s = seq_len[b];
        s = max(0, min(512, s));
        int pos = off[s] + atomicAdd(&f[s], 1);
        if (pos < 4096) g_order[pos] = b;
    }
    if (tid == 0) g_done = 0;
}

// ---------- kernel 1: forward; branchless chunks, ping-pong, 1-SHFL renorm ----------
__global__ void __launch_bounds__(256, 1) crf_forward(
    const float* __restrict__ pred,     // [B, T, 62]
    const int*   __restrict__ ref,      // [B, T]
    const int*   __restrict__ seq_len,  // [B]
    const float* __restrict__ trans,    // [64, 64]
    float* __restrict__ out,
    int B, int T)
{
    const int lane   = threadIdx.x & 31;
    const int warpIn = threadIdx.x >> 5;          // 0..7

    __shared__ __align__(16) float alphaSh[8][2][64];   // [warp][pingpong][state]
    __shared__ int s_last;
    __shared__ double s_red[256];

    // M columns (lane, lane+32) in registers: 64 x f32x2
    unsigned long long Mreg[64];
#pragma unroll
    for (int i = 0; i < 64; i++)
        Mreg[i] = *reinterpret_cast<const unsigned long long*>(&g_Mpack[i * 32 + lane]);

    const float T_lo = g_Mpack[lane * 32 + 31].y;          // exp(trans[lane][63])
    const float T_hi = g_Mpack[(lane + 32) * 32 + 31].y;   // exp(trans[lane+32][63])

    // complement row assignment: 2 warps/SMSP sum to ~513 steps
    const int half = (B + 1) >> 1;
    int idx;
    bool active;
    if (warpIn < 4) {
        idx = blockIdx.x * 4 + warpIn;
        active = (idx < half);
    } else {
        idx = B - 1 - (blockIdx.x * 4 + (warpIn - 4));
        active = (idx >= half && idx < B);
    }

    if (active) {
        const int b = g_order[idx];
        const int S = seq_len[b];
        const float* prow = pred + (size_t)b * T * 62;

        float* aP0 = alphaSh[warpIn][0];
        float* aP1 = alphaSh[warpIn][1];

        // init alpha = ones over 62 labels, C = -1000 (b_s floor)
        aP0[lane]      = 1.0f;
        aP0[lane + 32] = (lane < 30) ? 1.0f : 0.0f;
        __syncwarp();

        float C = -1000.0f;
        float escale = 1.0f;            // pending 1/s; consumed by next emission or finalize
        float v_lo = 1.0f, v_hi = (lane < 30) ? 1.0f : 0.0f;

        const int nfull = S >> 2;       // full 4-step chunks (branchless bodies)
        const int rem   = S & 3;        // 0..3 tail steps

        // one matvec step: reads aR, writes aW, applies emission e (w/ scale)
        auto step = [&](const float* aR, float* aW, float p_lo, float p_hi, float sc) {
            float e_lo = __expf(p_lo) * sc;
            float e_hi = (lane < 30) ? __expf(p_hi) * sc : 0.0f;
            unsigned long long a0 = 0, a1 = 0, a2 = 0, a3 = 0,
                               a4 = 0, a5 = 0, a6 = 0, a7 = 0;
#pragma unroll
            for (int i = 0; i < 64; i += 8) {
                float4 x = *reinterpret_cast<const float4*>(&aR[i]);
                float4 y = *reinterpret_cast<const float4*>(&aR[i + 4]);
                a0 = ffma2(pack2f(x.x, x.x), Mreg[i + 0], a0);
                a1 = ffma2(pack2f(x.y, x.y), Mreg[i + 1], a1);
                a2 = ffma2(pack2f(x.z, x.z), Mreg[i + 2], a2);
                a3 = ffma2(pack2f(x.w, x.w), Mreg[i + 3], a3);
                a4 = ffma2(pack2f(y.x, y.x), Mreg[i + 4], a4);
                a5 = ffma2(pack2f(y.y, y.y), Mreg[i + 5], a5);
                a6 = ffma2(pack2f(y.z, y.z), Mreg[i + 6], a6);
                a7 = ffma2(pack2f(y.w, y.w), Mreg[i + 7], a7);
            }
            unsigned long long acc =
                fadd2(fadd2(fadd2(a0, a1), fadd2(a2, a3)),
                      fadd2(fadd2(a4, a5), fadd2(a6, a7)));
            unsigned long long v2 = fmul2(acc, pack2f(e_lo, e_hi));
            unpack2f(v2, v_lo, v_hi);
            aW[lane]      = v_lo;
            aW[lane + 32] = v_hi;
            __syncwarp();              // single sync per step (ping-pong)
        };

        // prefetch tail emissions up front (latency fully hidden by main loop)
        float rlo[3], rhi[3];
#pragma unroll
        for (int j = 0; j < 3; j++) {
            int u = min(nfull * 4 + j, S - 1);
            const float* rp = prow + (size_t)u * 62;
            rlo[j] = rp[lane];
            rhi[j] = (lane < 30) ? rp[lane + 32] : 0.0f;
        }

        if (nfull > 0) {
            // triple-buffered emission prefetch; all indices in-bounds (u < 4*nfull <= S)
            float plo0[4], phi0[4], plo1[4], phi1[4], plo2[4], phi2[4];
            auto loadch = [&](float (&lo)[4], float (&hi)[4], int c) {
#pragma unroll
                for (int k = 0; k < 4; k++) {
                    const float* rp = prow + (size_t)(c * 4 + k) * 62;
                    lo[k] = rp[lane];
                    hi[k] = (lane < 30) ? rp[lane + 32] : 0.0f;
                }
            };

            loadch(plo0, phi0, 0);
            loadch(plo1, phi1, min(1, nfull - 1));

            for (int c = 0; c < nfull; c++) {
                loadch(plo2, phi2, min(c + 2, nfull - 1));   // clamped, branchless

                // 4 unconditional steps; ping-pong parity fixed per chunk
                step(aP0, aP1, plo0[0], phi0[0], escale);
                step(aP1, aP0, plo0[1], phi0[1], 1.0f);
                step(aP0, aP1, plo0[2], phi0[2], 1.0f);
                step(aP1, aP0, plo0[3], phi0[3], 1.0f);

                // cheap renorm: ANY positive lane-uniform scale is exact (C absorbs log).
                // Use lane 0's (v_lo+v_hi) = alpha[0]+alpha[32] > 0 — one SHFL, no tree.
                float s = __shfl_sync(0xffffffffu, v_lo + v_hi, 0);
                C += __logf(s);
                escale = __fdividef(1.0f, s);

#pragma unroll
                for (int k = 0; k < 4; k++) {
                    plo0[k] = plo1[k]; phi0[k] = phi1[k];
                    plo1[k] = plo2[k]; phi1[k] = phi2[k];
                }
            }
        }

        // remainder steps (0..3), emissions already in registers
        {
            float* rd = (nfull & 1) ? aP1 : aP0;   // buffer holding alpha after 4*nfull steps
            float* wr = (nfull & 1) ? aP0 : aP1;
            if (rem > 0) { step(rd, wr, rlo[0], rhi[0], escale); escale = 1.0f; }
            if (rem > 1) { step(wr, rd, rlo[1], rhi[1], 1.0f); }
            if (rem > 2) { step(rd, wr, rlo[2], rhi[2], 1.0f); }
        }

        // logZ = C + log( escale * sum_i v[i] * exp(trans[i,63]) )
        float z = warp_sum(v_lo * T_lo + v_hi * T_hi);
        float logZ = C + __logf(z * escale);

        // gold path score
        float gold = 0.0f;
        const int* refb = ref + (size_t)b * T;
        for (int t = lane; t < S; t += 32) {
            int rt = refb[t];
            gold += prow[(size_t)t * 62 + rt];             // emission
            int rp = (t == 0) ? 62 : refb[t - 1];          // start row at t=0
            gold += trans[rp * 64 + rt];                   // transition
        }
        if (lane == 0)
            gold += trans[refb[S - 1] * 64 + 63];          // final -> end
        gold = warp_sum(gold);

        if (lane == 0 && b < 4096)
            g_loss[b] = logZ - gold;
    }

    // ---- fused deterministic reduction: last CTA sums in fixed order ----
    __syncthreads();
    if (threadIdx.x == 0) {
        __threadfence();
        int v = atomicAdd(&g_done, 1);
        s_last = (v == gridDim.x - 1) ? 1 : 0;
    }
    __syncthreads();
    if (s_last) {
        __threadfence();
        double acc = 0.0;
        for (int i = threadIdx.x; i < B; i += 256)
            acc += (double)g_loss[i];
        s_red[threadIdx.x] = acc;
        __syncthreads();
        for (int st = 128; st >= 1; st >>= 1) {
            if (threadIdx.x < st) s_red[threadIdx.x] += s_red[threadIdx.x + st];
            __syncthreads();
        }
        if (threadIdx.x == 0) out[0] = (float)s_red[0];
    }
}

extern "C" void kernel_launch(void* const* d_in, const int* in_sizes, int n_in,
                              void* d_out, int out_size) {
    const float* pred   = (const float*)d_in[0];
    const int*   ref    = (const int*)d_in[1];
    const int*   seqlen = (const int*)d_in[2];
    const float* trans  = (const float*)d_in[3];

    int B = in_sizes[2];            // 1024
    int T = in_sizes[1] / B;        // 512

    int ctas = ((B + 1) / 2 + 3) / 4;   // 128 for B=1024

    crf_prep<<<1, 1024>>>(trans, seqlen, B);
    crf_forward<<<ctas, 256>>>(pred, ref, seqlen, trans, (float*)d_out, B, T);
}

// round 16
// speedup vs baseline: 1.4244x; 1.0109x over previous
#include <cuda_runtime.h>
#include <cstdint>

// Scratch (no cudaMalloc allowed)
__device__ float2 g_Mpack[64 * 32];   // g_Mpack[i*32+l] = (exp(T[i][l]), exp(T[i][l+32]))
__device__ float  g_loss[4096];
__device__ int    g_order[4096];
__device__ int    g_done;

// ---------- f32x2 packed math ----------
static __device__ __forceinline__ unsigned long long pack2f(float lo, float hi) {
    unsigned long long r;
    asm("mov.b64 %0, {%1, %2};" : "=l"(r) : "f"(lo), "f"(hi));
    return r;
}
static __device__ __forceinline__ void unpack2f(unsigned long long v, float& lo, float& hi) {
    asm("mov.b64 {%0, %1}, %2;" : "=f"(lo), "=f"(hi) : "l"(v));
}
static __device__ __forceinline__ unsigned long long ffma2(unsigned long long a,
                                                           unsigned long long b,
                                                           unsigned long long c) {
    unsigned long long d;
    asm("fma.rn.f32x2 %0, %1, %2, %3;" : "=l"(d) : "l"(a), "l"(b), "l"(c));
    return d;
}
static __device__ __forceinline__ unsigned long long fadd2(unsigned long long a,
                                                           unsigned long long b) {
    unsigned long long d;
    asm("add.rn.f32x2 %0, %1, %2;" : "=l"(d) : "l"(a), "l"(b));
    return d;
}
static __device__ __forceinline__ unsigned long long fmul2(unsigned long long a,
                                                           unsigned long long b) {
    unsigned long long d;
    asm("mul.rn.f32x2 %0, %1, %2;" : "=l"(d) : "l"(a), "l"(b));
    return d;
}
// full warp sum (5-SHFL tree) — used only once per row
static __device__ __forceinline__ float warp_sum(float v) {
#pragma unroll
    for (int m = 16; m >= 1; m >>= 1)
        v += __shfl_xor_sync(0xffffffffu, v, m);
    return v;
}

// ---------- kernel 0: fused prep (Mpack + hist + scan + scatter + counter reset) ----------
__global__ void __launch_bounds__(1024) crf_prep(const float* __restrict__ trans,
                                                 const int* __restrict__ seq_len, int B) {
    __shared__ int h[513], f[513], off[513];
    __shared__ int sc[1024];
    const int tid = threadIdx.x;

    if (tid < 513) { h[tid] = 0; f[tid] = 0; }
    for (int idx = tid; idx < 64 * 32; idx += 1024) {
        int i = idx >> 5, l = idx & 31;
        g_Mpack[idx] = make_float2(__expf(trans[i * 64 + l]),
                                   __expf(trans[i * 64 + l + 32]));
    }
    __syncthreads();

    for (int b = tid; b < B; b += 1024) {
        int s = seq_len[b];
        s = max(0, min(512, s));
        atomicAdd(&h[s], 1);
    }
    __syncthreads();

    sc[tid] = (tid < 513) ? h[512 - tid] : 0;   // reversed (descending S)
    __syncthreads();
    for (int d = 1; d < 1024; d <<= 1) {
        int v = (tid >= d) ? sc[tid - d] : 0;
        __syncthreads();
        sc[tid] += v;
        __syncthreads();
    }
    if (tid < 513) off[512 - tid] = sc[tid] - h[512 - tid];
    __syncthreads();

    for (int b = tid; b < B; b += 1024) {
        int s = seq_len[b];
        s = max(0, min(512, s));
        int pos = off[s] + atomicAdd(&f[s], 1);
        if (pos < 4096) g_order[pos] = b;
    }
    if (tid == 0) g_done = 0;
}

// ---------- kernel 1: forward; branchless chunks, ping-pong, 1-SHFL renorm ----------
__global__ void __launch_bounds__(256, 1) crf_forward(
    const float* __restrict__ pred,     // [B, T, 62]
    const int*   __restrict__ ref,      // [B, T]
    const int*   __restrict__ seq_len,  // [B]
    const float* __restrict__ trans,    // [64, 64]
    float* __restrict__ out,
    int B, int T)
{
    const int lane   = threadIdx.x & 31;
    const int warpIn = threadIdx.x >> 5;          // 0..7

    __shared__ __align__(16) float alphaSh[8][2][64];   // [warp][pingpong][state]
    __shared__ int s_last;
    __shared__ double s_red[256];

    // M columns (lane, lane+32) in registers: 64 x f32x2
    unsigned long long Mreg[64];
#pragma unroll
    for (int i = 0; i < 64; i++)
        Mreg[i] = *reinterpret_cast<const unsigned long long*>(&g_Mpack[i * 32 + lane]);

    const float T_lo = g_Mpack[lane * 32 + 31].y;          // exp(trans[lane][63])
    const float T_hi = g_Mpack[(lane + 32) * 32 + 31].y;   // exp(trans[lane+32][63])

    // complement row assignment: 2 warps/SMSP sum to ~513 steps
    const int half = (B + 1) >> 1;
    int idx;
    bool active;
    if (warpIn < 4) {
        idx = blockIdx.x * 4 + warpIn;
        active = (idx < half);
    } else {
        idx = B - 1 - (blockIdx.x * 4 + (warpIn - 4));
        active = (idx >= half && idx < B);
    }

    if (active) {
        const int b = g_order[idx];
        const int S = seq_len[b];
        const float* prow = pred + (size_t)b * T * 62;

        float* aP0 = alphaSh[warpIn][0];
        float* aP1 = alphaSh[warpIn][1];

        // init alpha = ones over 62 labels, C = -1000 (b_s floor)
        aP0[lane]      = 1.0f;
        aP0[lane + 32] = (lane < 30) ? 1.0f : 0.0f;
        __syncwarp();

        float C = -1000.0f;
        float escale = 1.0f;            // pending 1/s; consumed by next emission or finalize
        float v_lo = 1.0f, v_hi = (lane < 30) ? 1.0f : 0.0f;

        const int nfull = S >> 2;       // full 4-step chunks (branchless bodies)
        const int rem   = S & 3;        // 0..3 tail steps

        // one matvec step: reads aR, writes aW, applies emission e (w/ scale)
        auto step = [&](const float* aR, float* aW, float p_lo, float p_hi, float sc) {
            float e_lo = __expf(p_lo) * sc;
            float e_hi = (lane < 30) ? __expf(p_hi) * sc : 0.0f;
            unsigned long long a0 = 0, a1 = 0, a2 = 0, a3 = 0,
                               a4 = 0, a5 = 0, a6 = 0, a7 = 0;
#pragma unroll
            for (int i = 0; i < 64; i += 8) {
                float4 x = *reinterpret_cast<const float4*>(&aR[i]);
                float4 y = *reinterpret_cast<const float4*>(&aR[i + 4]);
                a0 = ffma2(pack2f(x.x, x.x), Mreg[i + 0], a0);
                a1 = ffma2(pack2f(x.y, x.y), Mreg[i + 1], a1);
                a2 = ffma2(pack2f(x.z, x.z), Mreg[i + 2], a2);
                a3 = ffma2(pack2f(x.w, x.w), Mreg[i + 3], a3);
                a4 = ffma2(pack2f(y.x, y.x), Mreg[i + 4], a4);
                a5 = ffma2(pack2f(y.y, y.y), Mreg[i + 5], a5);
                a6 = ffma2(pack2f(y.z, y.z), Mreg[i + 6], a6);
                a7 = ffma2(pack2f(y.w, y.w), Mreg[i + 7], a7);
            }
            unsigned long long acc =
                fadd2(fadd2(fadd2(a0, a1), fadd2(a2, a3)),
                      fadd2(fadd2(a4, a5), fadd2(a6, a7)));
            unsigned long long v2 = fmul2(acc, pack2f(e_lo, e_hi));
            unpack2f(v2, v_lo, v_hi);
            aW[lane]      = v_lo;
            aW[lane + 32] = v_hi;
            __syncwarp();              // single sync per step (ping-pong)
        };

        // prefetch tail emissions up front (latency fully hidden by main loop)
        float rlo[3], rhi[3];
#pragma unroll
        for (int j = 0; j < 3; j++) {
            int u = min(nfull * 4 + j, S - 1);
            const float* rp = prow + (size_t)u * 62;
            rlo[j] = rp[lane];
            rhi[j] = (lane < 30) ? rp[lane + 32] : 0.0f;
        }

        if (nfull > 0) {
            // triple-buffered emission prefetch; all indices in-bounds (u < 4*nfull <= S)
            float plo0[4], phi0[4], plo1[4], phi1[4], plo2[4], phi2[4];
            auto loadch = [&](float (&lo)[4], float (&hi)[4], int c) {
#pragma unroll
                for (int k = 0; k < 4; k++) {
                    const float* rp = prow + (size_t)(c * 4 + k) * 62;
                    lo[k] = rp[lane];
                    hi[k] = (lane < 30) ? rp[lane + 32] : 0.0f;
                }
            };

            loadch(plo0, phi0, 0);
            loadch(plo1, phi1, min(1, nfull - 1));

            for (int c = 0; c < nfull; c++) {
                loadch(plo2, phi2, min(c + 2, nfull - 1));   // clamped, branchless

                // 4 unconditional steps; ping-pong parity fixed per chunk
                step(aP0, aP1, plo0[0], phi0[0], escale);
                step(aP1, aP0, plo0[1], phi0[1], 1.0f);
                step(aP0, aP1, plo0[2], phi0[2], 1.0f);
                step(aP1, aP0, plo0[3], phi0[3], 1.0f);

                // cheap renorm: ANY positive lane-uniform scale is exact (C absorbs log).
                float s = __shfl_sync(0xffffffffu, v_lo + v_hi, 0);
                C += __logf(s);
                escale = __fdividef(1.0f, s);

#pragma unroll
                for (int k = 0; k < 4; k++) {
                    plo0[k] = plo1[k]; phi0[k] = phi1[k];
                    plo1[k] = plo2[k]; phi1[k] = phi2[k];
                }
            }
        }

        // remainder steps (0..3), emissions already in registers
        {
            float* rd = (nfull & 1) ? aP1 : aP0;   // buffer holding alpha after 4*nfull steps
            float* wr = (nfull & 1) ? aP0 : aP1;
            if (rem > 0) { step(rd, wr, rlo[0], rhi[0], escale); escale = 1.0f; }
            if (rem > 1) { step(wr, rd, rlo[1], rhi[1], 1.0f); }
            if (rem > 2) { step(rd, wr, rlo[2], rhi[2], 1.0f); }
        }

        // logZ = C + log( escale * sum_i v[i] * exp(trans[i,63]) )
        float z = warp_sum(v_lo * T_lo + v_hi * T_hi);
        float logZ = C + __logf(z * escale);

        // ---- gold path score, MLP-restructured (no serial LDG->FADD chains) ----
        float gold = 0.0f;
        const int* refb = ref + (size_t)b * T;
        if (S <= 512) {
            // phase 1: all label loads issued together (MLP=16)
            int rts[16];
            bool act[16];
#pragma unroll
            for (int j = 0; j < 16; j++) {
                int t = lane + 32 * j;
                act[j] = (t < S);
                rts[j] = refb[min(t, S - 1)];
            }
            // derive rp = ref[t-1] by SHFL (lane l-1 holds it; lane 0 borrows
            // lane 31 of the previous batch; t=0 uses start state 62)
            int rps[16];
#pragma unroll
            for (int j = 0; j < 16; j++) {
                int up = __shfl_up_sync(0xffffffffu, rts[j], 1);
                int prevhi = (j > 0) ? __shfl_sync(0xffffffffu, rts[j - 1], 31) : 62;
                rps[j] = (lane == 0) ? prevhi : up;
            }
            // phase 2+3: gathers (all independent) + accumulate
            float em[16], tr[16];
#pragma unroll
            for (int j = 0; j < 16; j++) {
                int t = lane + 32 * j;
                int tc = min(t, S - 1);
                em[j] = act[j] ? prow[(size_t)tc * 62 + rts[j]] : 0.0f;
                tr[j] = act[j] ? trans[rps[j] * 64 + rts[j]] : 0.0f;
            }
#pragma unroll
            for (int j = 0; j < 16; j++)
                gold += em[j] + tr[j];
        } else {
            for (int t = lane; t < S; t += 32) {
                int rt = refb[t];
                gold += prow[(size_t)t * 62 + rt];
                int rp = (t == 0) ? 62 : refb[t - 1];
                gold += trans[rp * 64 + rt];
            }
        }
        if (lane == 0)
            gold += trans[refb[S - 1] * 64 + 63];          // final -> end
        gold = warp_sum(gold);

        if (lane == 0 && b < 4096)
            g_loss[b] = logZ - gold;
    }

    // ---- fused deterministic reduction: last CTA sums in fixed order ----
    __syncthreads();
    if (threadIdx.x == 0) {
        __threadfence();
        int v = atomicAdd(&g_done, 1);
        s_last = (v == gridDim.x - 1) ? 1 : 0;
    }
    __syncthreads();
    if (s_last) {
        __threadfence();
        double acc = 0.0;
        for (int i = threadIdx.x; i < B; i += 256)
            acc += (double)g_loss[i];
        s_red[threadIdx.x] = acc;
        __syncthreads();
        for (int st = 128; st >= 1; st >>= 1) {
            if (threadIdx.x < st) s_red[threadIdx.x] += s_red[threadIdx.x + st];
            __syncthreads();
        }
        if (threadIdx.x == 0) out[0] = (float)s_red[0];
    }
}

extern "C" void kernel_launch(void* const* d_in, const int* in_sizes, int n_in,
                              void* d_out, int out_size) {
    const float* pred   = (const float*)d_in[0];
    const int*   ref    = (const int*)d_in[1];
    const int*   seqlen = (const int*)d_in[2];
    const float* trans  = (const float*)d_in[3];

    int B = in_sizes[2];            // 1024
    int T = in_sizes[1] / B;        // 512

    int ctas = ((B + 1) / 2 + 3) / 4;   // 128 for B=1024

    crf_prep<<<1, 1024>>>(trans, seqlen, B);
    crf_forward<<<ctas, 256>>>(pred, ref, seqlen, trans, (float*)d_out, B, T);
}